// round 7
// baseline (speedup 1.0000x reference)
#include <cuda_runtime.h>
#include <math.h>

// ---------------------------------------------------------------------------
// Weighted Kabsch, fully fused: one CTA per batch streams the batch's points
// (HBM-bound), block-reduces 16 sufficient statistics, then thread 0 performs
// the fp32 3x3 SVD + rotation/translation epilogue in the HBM shadow of the
// other in-flight CTAs. Single kernel launch, no global scratch round-trip.
// ---------------------------------------------------------------------------

#define RED_THREADS 256

__device__ __forceinline__ float det3f(const float m[3][3]) {
    return m[0][0] * (m[1][1] * m[2][2] - m[1][2] * m[2][1])
         - m[0][1] * (m[1][0] * m[2][2] - m[1][2] * m[2][0])
         + m[0][2] * (m[1][0] * m[2][1] - m[1][1] * m[2][0]);
}

__global__ void __launch_bounds__(RED_THREADS)
kabsch_kernel(const float* __restrict__ src,
              const float* __restrict__ tgt,
              const float* __restrict__ wts,
              float* __restrict__ out,
              int N, int B)
{
    const int b = blockIdx.x;
    const float4* s4 = (const float4*)(src + (size_t)b * N * 3);
    const float4* t4 = (const float4*)(tgt + (size_t)b * N * 3);
    const float4* w4 = (const float4*)(wts + (size_t)b * N);

    float acc[16];
#pragma unroll
    for (int i = 0; i < 16; i++) acc[i] = 0.f;

    const int tid = threadIdx.x;
    const int ngroups = N >> 2;  // N divisible by 4

    for (int g = tid; g < ngroups; g += RED_THREADS) {
        float4 wv = w4[g];
        float4 a0 = s4[g * 3 + 0];
        float4 a1 = s4[g * 3 + 1];
        float4 a2 = s4[g * 3 + 2];
        float4 b0 = t4[g * 3 + 0];
        float4 b1 = t4[g * 3 + 1];
        float4 b2 = t4[g * 3 + 2];

        const float sx[4][3] = {{a0.x, a0.y, a0.z},
                                {a0.w, a1.x, a1.y},
                                {a1.z, a1.w, a2.x},
                                {a2.y, a2.z, a2.w}};
        const float tx[4][3] = {{b0.x, b0.y, b0.z},
                                {b0.w, b1.x, b1.y},
                                {b1.z, b1.w, b2.x},
                                {b2.y, b2.z, b2.w}};
        const float wa[4] = {wv.x, wv.y, wv.z, wv.w};

#pragma unroll
        for (int p = 0; p < 4; p++) {
            const float w = wa[p];
            const float s0 = sx[p][0], s1 = sx[p][1], s2 = sx[p][2];
            const float wt0 = w * tx[p][0];
            const float wt1 = w * tx[p][1];
            const float wt2 = w * tx[p][2];
            acc[0] += w;
            acc[1] += w * s0;  acc[2] += w * s1;  acc[3] += w * s2;
            acc[4] += wt0;     acc[5] += wt1;     acc[6] += wt2;
            acc[7]  += wt0 * s0;  acc[8]  += wt0 * s1;  acc[9]  += wt0 * s2;
            acc[10] += wt1 * s0;  acc[11] += wt1 * s1;  acc[12] += wt1 * s2;
            acc[13] += wt2 * s0;  acc[14] += wt2 * s1;  acc[15] += wt2 * s2;
        }
    }

    // warp reduce
#pragma unroll
    for (int i = 0; i < 16; i++) {
#pragma unroll
        for (int o = 16; o > 0; o >>= 1)
            acc[i] += __shfl_down_sync(0xffffffffu, acc[i], o);
    }

    __shared__ float smem[RED_THREADS / 32][16];
    const int warp = tid >> 5;
    const int lane = tid & 31;
    if (lane == 0) {
#pragma unroll
        for (int i = 0; i < 16; i++) smem[warp][i] = acc[i];
    }
    __syncthreads();

    if (tid != 0) return;

    // ---- thread 0: finalize 16 stats and run the 3x3 SVD epilogue ----
    float s[16];
#pragma unroll
    for (int i = 0; i < 16; i++) {
        float v = smem[0][i];
#pragma unroll
        for (int w = 1; w < RED_THREADS / 32; w++) v += smem[w][i];
        s[i] = v;
    }

    const float Sw = s[0];
    const float Sx[3] = {s[1], s[2], s[3]};
    const float Tx[3] = {s[4], s[5], s[6]};
    const float M[3][3] = {{s[7], s[8], s[9]},
                           {s[10], s[11], s[12]},
                           {s[13], s[14], s[15]}};

    const float w = Sw + 1e-4f;
    const float winv = 1.0f / w;
    float sc[3], tc[3];
#pragma unroll
    for (int i = 0; i < 3; i++) { sc[i] = Sx[i] * winv; tc[i] = Tx[i] * winv; }

    // A = weighted cross-covariance (tgt rows, src cols), centered
    float A[3][3];
#pragma unroll
    for (int i = 0; i < 3; i++)
#pragma unroll
        for (int j = 0; j < 3; j++)
            A[i][j] = (M[i][j] - tc[i] * Sx[j] - Tx[i] * sc[j] + Sw * tc[i] * sc[j]) * winv;

    // Bm = A^T A (symmetric PSD)
    float Bm[3][3];
#pragma unroll
    for (int i = 0; i < 3; i++)
#pragma unroll
        for (int j = 0; j < 3; j++)
            Bm[i][j] = A[0][i] * A[0][j] + A[1][i] * A[1][j] + A[2][i] * A[2][j];

    float V[3][3] = {{1, 0, 0}, {0, 1, 0}, {0, 0, 1}};

    // cyclic Jacobi, 6 sweeps (quadratic convergence, 3x3)
#pragma unroll 1
    for (int sweep = 0; sweep < 6; sweep++) {
#pragma unroll
        for (int pair = 0; pair < 3; pair++) {
            const int p = (pair == 2) ? 1 : 0;
            const int q = (pair == 0) ? 1 : 2;
            const float apq = Bm[p][q];
            if (fabsf(apq) < 1e-30f) continue;
            const float app = Bm[p][p], aqq = Bm[q][q];
            const float tau = (aqq - app) / (2.0f * apq);
            const float t = ((tau >= 0.0f) ? 1.0f : -1.0f) /
                            (fabsf(tau) + sqrtf(1.0f + tau * tau));
            const float c = rsqrtf(1.0f + t * t);
            const float sn = t * c;
            // B <- J^T B J
#pragma unroll
            for (int k = 0; k < 3; k++) {
                const float bkp = Bm[k][p], bkq = Bm[k][q];
                Bm[k][p] = c * bkp - sn * bkq;
                Bm[k][q] = sn * bkp + c * bkq;
            }
#pragma unroll
            for (int k = 0; k < 3; k++) {
                const float bpk = Bm[p][k], bqk = Bm[q][k];
                Bm[p][k] = c * bpk - sn * bqk;
                Bm[q][k] = sn * bpk + c * bqk;
            }
            // V <- V J
#pragma unroll
            for (int k = 0; k < 3; k++) {
                const float vkp = V[k][p], vkq = V[k][q];
                V[k][p] = c * vkp - sn * vkq;
                V[k][q] = sn * vkp + c * vkq;
            }
        }
    }

    float lam[3] = {Bm[0][0], Bm[1][1], Bm[2][2]};
    // sort eigenvalues descending (with V column swaps) to match jnp svd order
#pragma unroll
    for (int i = 0; i < 2; i++)
#pragma unroll
        for (int j = 0; j < 2 - i; j++)
            if (lam[j] < lam[j + 1]) {
                float tl = lam[j]; lam[j] = lam[j + 1]; lam[j + 1] = tl;
#pragma unroll
                for (int k = 0; k < 3; k++) {
                    float tv = V[k][j]; V[k][j] = V[k][j + 1]; V[k][j + 1] = tv;
                }
            }

    // U columns: A v_k / |A v_k|
    float U[3][3];
    float norms[3];
#pragma unroll
    for (int k = 0; k < 3; k++) {
        float uv[3];
#pragma unroll
        for (int i = 0; i < 3; i++)
            uv[i] = A[i][0] * V[0][k] + A[i][1] * V[1][k] + A[i][2] * V[2][k];
        const float nsq = uv[0] * uv[0] + uv[1] * uv[1] + uv[2] * uv[2];
        norms[k] = sqrtf(nsq);
        const float inv = (nsq > 1e-36f) ? rsqrtf(nsq) : 0.0f;
#pragma unroll
        for (int i = 0; i < 3; i++) U[i][k] = uv[i] * inv;
    }
    // degenerate smallest singular value -> complete right-handed frame
    if (norms[2] < 1e-7f * (norms[0] + 1e-30f)) {
        U[0][2] = U[1][0] * U[2][1] - U[2][0] * U[1][1];
        U[1][2] = U[2][0] * U[0][1] - U[0][0] * U[2][1];
        U[2][2] = U[0][0] * U[1][1] - U[1][0] * U[0][1];
    }

    const float d = det3f(U) * det3f(V);

    // R = U diag(1,1,d) V^T
    float R[3][3];
#pragma unroll
    for (int i = 0; i < 3; i++)
#pragma unroll
        for (int j = 0; j < 3; j++)
            R[i][j] = U[i][0] * V[j][0] + U[i][1] * V[j][1] + d * U[i][2] * V[j][2];

    // t1 = src_centroid - R^T tgt_centroid ; t = -R t1
    float t1[3], t[3];
#pragma unroll
    for (int i = 0; i < 3; i++)
        t1[i] = sc[i] - (R[0][i] * tc[0] + R[1][i] * tc[1] + R[2][i] * tc[2]);
#pragma unroll
    for (int i = 0; i < 3; i++)
        t[i] = -(R[i][0] * t1[0] + R[i][1] * t1[1] + R[i][2] * t1[2]);

    // outputs: R flattened (B,3,3) then t flattened (B,3,1)
    float* Rout = out + (size_t)b * 9;
    float* Tout = out + (size_t)B * 9 + (size_t)b * 3;
#pragma unroll
    for (int i = 0; i < 3; i++)
#pragma unroll
        for (int j = 0; j < 3; j++)
            Rout[i * 3 + j] = R[i][j];
#pragma unroll
    for (int i = 0; i < 3; i++) Tout[i] = t[i];
}

// ---------------------------------------------------------------------------

extern "C" void kernel_launch(void* const* d_in, const int* in_sizes, int n_in,
                              void* d_out, int out_size)
{
    const float* src = (const float*)d_in[0];
    const float* tgt = (const float*)d_in[1];
    const float* wts = (const float*)d_in[2];
    float* out = (float*)d_out;

    const int B = out_size / 12;            // 9 (R) + 3 (t) per batch
    const int N = in_sizes[2] / B;          // weights are (B,1,N)

    kabsch_kernel<<<B, RED_THREADS>>>(src, tgt, wts, out, N, B);
}

// round 8
// speedup vs baseline: 1.0758x; 1.0758x over previous
#include <cuda_runtime.h>
#include <math.h>
#include <stdint.h>

// ---------------------------------------------------------------------------
// Weighted Kabsch, fused + smem-staged streaming.
// Stage 1 per CTA: cp.async-coalesced tiles (double buffered) -> 16 sufficient
// statistics (HBM-bound). Stage 2: thread 0 runs a fast fp32 3x3 SVD epilogue.
// ---------------------------------------------------------------------------

#define RED_THREADS 256
#define TILE 512   // points per tile

__device__ __forceinline__ void cp16(uint32_t saddr, const void* gaddr) {
    asm volatile("cp.async.cg.shared.global [%0], [%1], 16;" :: "r"(saddr), "l"(gaddr));
}
__device__ __forceinline__ void cp_commit() {
    asm volatile("cp.async.commit_group;");
}
template <int NG> __device__ __forceinline__ void cp_wait() {
    asm volatile("cp.async.wait_group %0;" :: "n"(NG));
}

struct SmemLayout {
    float src[2][TILE * 3];   // 12 KB
    float tgt[2][TILE * 3];   // 12 KB
    float wgt[2][TILE];       // 4 KB
    float red[RED_THREADS / 32][16];
};

__device__ __forceinline__ float det3f(const float m[3][3]) {
    return m[0][0] * (m[1][1] * m[2][2] - m[1][2] * m[2][1])
         - m[0][1] * (m[1][0] * m[2][2] - m[1][2] * m[2][0])
         + m[0][2] * (m[1][0] * m[2][1] - m[1][1] * m[2][0]);
}

__device__ __forceinline__ void stage_tile(SmemLayout* sm, int bb,
                                           const float4* __restrict__ s4,
                                           const float4* __restrict__ t4,
                                           const float4* __restrict__ w4,
                                           int tile, int npts, int tid)
{
    const int nf4c = (npts * 3) >> 2;         // coord float4 count this tile
    const int nf4w = npts >> 2;               // weight float4 count
    const int cbase = tile * (TILE * 3 / 4);
    const int wbase = tile * (TILE / 4);
    uint32_t sS = (uint32_t)__cvta_generic_to_shared(&sm->src[bb][0]);
    uint32_t sT = (uint32_t)__cvta_generic_to_shared(&sm->tgt[bb][0]);
    uint32_t sW = (uint32_t)__cvta_generic_to_shared(&sm->wgt[bb][0]);
    for (int i = tid; i < nf4c; i += RED_THREADS) {
        cp16(sS + i * 16, s4 + cbase + i);
        cp16(sT + i * 16, t4 + cbase + i);
    }
    for (int i = tid; i < nf4w; i += RED_THREADS)
        cp16(sW + i * 16, w4 + wbase + i);
    cp_commit();
}

__global__ void __launch_bounds__(RED_THREADS)
kabsch_kernel(const float* __restrict__ src,
              const float* __restrict__ tgt,
              const float* __restrict__ wts,
              float* __restrict__ out,
              int N, int B)
{
    __shared__ SmemLayout sm;

    const int b = blockIdx.x;
    const int tid = threadIdx.x;
    const float4* s4 = (const float4*)(src + (size_t)b * N * 3);
    const float4* t4 = (const float4*)(tgt + (size_t)b * N * 3);
    const float4* w4 = (const float4*)(wts + (size_t)b * N);

    const int ntiles = (N + TILE - 1) / TILE;

    float acc[16];
#pragma unroll
    for (int i = 0; i < 16; i++) acc[i] = 0.f;

    // prologue: stage tile 0
    stage_tile(&sm, 0, s4, t4, w4, 0, min(TILE, N), tid);

    for (int t = 0; t < ntiles; t++) {
        const int bb = t & 1;
        if (t + 1 < ntiles) {
            stage_tile(&sm, bb ^ 1, s4, t4, w4, t + 1,
                       min(TILE, N - (t + 1) * TILE), tid);
            cp_wait<1>();
        } else {
            cp_wait<0>();
        }
        __syncthreads();

        const int npts = min(TILE, N - t * TILE);
        const float* S = sm.src[bb];
        const float* T = sm.tgt[bb];
        const float* W = sm.wgt[bb];

        // lane stride = 3 floats (gcd(3,32)=1) -> bank-conflict-free LDS
        for (int p = tid; p < npts; p += RED_THREADS) {
            const float w  = W[p];
            const float s0 = S[p * 3 + 0], s1 = S[p * 3 + 1], s2 = S[p * 3 + 2];
            const float x0 = T[p * 3 + 0], x1 = T[p * 3 + 1], x2 = T[p * 3 + 2];
            const float wt0 = w * x0, wt1 = w * x1, wt2 = w * x2;
            acc[0] += w;
            acc[1] += w * s0;  acc[2] += w * s1;  acc[3] += w * s2;
            acc[4] += wt0;     acc[5] += wt1;     acc[6] += wt2;
            acc[7]  += wt0 * s0;  acc[8]  += wt0 * s1;  acc[9]  += wt0 * s2;
            acc[10] += wt1 * s0;  acc[11] += wt1 * s1;  acc[12] += wt1 * s2;
            acc[13] += wt2 * s0;  acc[14] += wt2 * s1;  acc[15] += wt2 * s2;
        }
        __syncthreads();
    }

    // warp reduce
#pragma unroll
    for (int i = 0; i < 16; i++) {
#pragma unroll
        for (int o = 16; o > 0; o >>= 1)
            acc[i] += __shfl_down_sync(0xffffffffu, acc[i], o);
    }

    const int warp = tid >> 5;
    const int lane = tid & 31;
    if (lane == 0) {
#pragma unroll
        for (int i = 0; i < 16; i++) sm.red[warp][i] = acc[i];
    }
    __syncthreads();

    if (tid != 0) return;

    // ---- thread 0: finalize stats, fast fp32 3x3 SVD + epilogue ----
    float s[16];
#pragma unroll
    for (int i = 0; i < 16; i++) {
        float v = sm.red[0][i];
#pragma unroll
        for (int w = 1; w < RED_THREADS / 32; w++) v += sm.red[w][i];
        s[i] = v;
    }

    const float Sw = s[0];
    const float Sx[3] = {s[1], s[2], s[3]};
    const float Tx[3] = {s[4], s[5], s[6]};
    const float M[3][3] = {{s[7], s[8], s[9]},
                           {s[10], s[11], s[12]},
                           {s[13], s[14], s[15]}};

    const float w = Sw + 1e-4f;
    const float winv = __fdividef(1.0f, w);
    float sc[3], tc[3];
#pragma unroll
    for (int i = 0; i < 3; i++) { sc[i] = Sx[i] * winv; tc[i] = Tx[i] * winv; }

    float A[3][3];
#pragma unroll
    for (int i = 0; i < 3; i++)
#pragma unroll
        for (int j = 0; j < 3; j++)
            A[i][j] = (M[i][j] - tc[i] * Sx[j] - Tx[i] * sc[j] + Sw * tc[i] * sc[j]) * winv;

    float Bm[3][3];
#pragma unroll
    for (int i = 0; i < 3; i++)
#pragma unroll
        for (int j = 0; j < 3; j++)
            Bm[i][j] = A[0][i] * A[0][j] + A[1][i] * A[1][j] + A[2][i] * A[2][j];

    float V[3][3] = {{1, 0, 0}, {0, 1, 0}, {0, 0, 1}};

    // cyclic Jacobi, 5 sweeps, fast divides, convergence skip
#pragma unroll 1
    for (int sweep = 0; sweep < 5; sweep++) {
#pragma unroll
        for (int pair = 0; pair < 3; pair++) {
            const int p = (pair == 2) ? 1 : 0;
            const int q = (pair == 0) ? 1 : 2;
            const float apq = Bm[p][q];
            const float app = Bm[p][p], aqq = Bm[q][q];
            if (apq * apq <= 1e-22f * app * aqq + 1e-38f) continue;
            const float tau = __fdividef(aqq - app, 2.0f * apq);
            const float t = __fdividef((tau >= 0.0f) ? 1.0f : -1.0f,
                                       fabsf(tau) + sqrtf(1.0f + tau * tau));
            const float c = rsqrtf(1.0f + t * t);
            const float sn = t * c;
#pragma unroll
            for (int k = 0; k < 3; k++) {
                const float bkp = Bm[k][p], bkq = Bm[k][q];
                Bm[k][p] = c * bkp - sn * bkq;
                Bm[k][q] = sn * bkp + c * bkq;
            }
#pragma unroll
            for (int k = 0; k < 3; k++) {
                const float bpk = Bm[p][k], bqk = Bm[q][k];
                Bm[p][k] = c * bpk - sn * bqk;
                Bm[q][k] = sn * bpk + c * bqk;
            }
#pragma unroll
            for (int k = 0; k < 3; k++) {
                const float vkp = V[k][p], vkq = V[k][q];
                V[k][p] = c * vkp - sn * vkq;
                V[k][q] = sn * vkp + c * vkq;
            }
        }
    }

    float lam[3] = {Bm[0][0], Bm[1][1], Bm[2][2]};
#pragma unroll
    for (int i = 0; i < 2; i++)
#pragma unroll
        for (int j = 0; j < 2 - i; j++)
            if (lam[j] < lam[j + 1]) {
                float tl = lam[j]; lam[j] = lam[j + 1]; lam[j + 1] = tl;
#pragma unroll
                for (int k = 0; k < 3; k++) {
                    float tv = V[k][j]; V[k][j] = V[k][j + 1]; V[k][j + 1] = tv;
                }
            }

    float U[3][3];
    float norms[3];
#pragma unroll
    for (int k = 0; k < 3; k++) {
        float uv[3];
#pragma unroll
        for (int i = 0; i < 3; i++)
            uv[i] = A[i][0] * V[0][k] + A[i][1] * V[1][k] + A[i][2] * V[2][k];
        const float nsq = uv[0] * uv[0] + uv[1] * uv[1] + uv[2] * uv[2];
        norms[k] = sqrtf(nsq);
        const float inv = (nsq > 1e-36f) ? rsqrtf(nsq) : 0.0f;
#pragma unroll
        for (int i = 0; i < 3; i++) U[i][k] = uv[i] * inv;
    }
    if (norms[2] < 1e-7f * (norms[0] + 1e-30f)) {
        U[0][2] = U[1][0] * U[2][1] - U[2][0] * U[1][1];
        U[1][2] = U[2][0] * U[0][1] - U[0][0] * U[2][1];
        U[2][2] = U[0][0] * U[1][1] - U[1][0] * U[0][1];
    }

    const float d = det3f(U) * det3f(V);

    float R[3][3];
#pragma unroll
    for (int i = 0; i < 3; i++)
#pragma unroll
        for (int j = 0; j < 3; j++)
            R[i][j] = U[i][0] * V[j][0] + U[i][1] * V[j][1] + d * U[i][2] * V[j][2];

    float t1[3], t[3];
#pragma unroll
    for (int i = 0; i < 3; i++)
        t1[i] = sc[i] - (R[0][i] * tc[0] + R[1][i] * tc[1] + R[2][i] * tc[2]);
#pragma unroll
    for (int i = 0; i < 3; i++)
        t[i] = -(R[i][0] * t1[0] + R[i][1] * t1[1] + R[i][2] * t1[2]);

    float* Rout = out + (size_t)b * 9;
    float* Tout = out + (size_t)B * 9 + (size_t)b * 3;
#pragma unroll
    for (int i = 0; i < 3; i++)
#pragma unroll
        for (int j = 0; j < 3; j++)
            Rout[i * 3 + j] = R[i][j];
#pragma unroll
    for (int i = 0; i < 3; i++) Tout[i] = t[i];
}

// ---------------------------------------------------------------------------

extern "C" void kernel_launch(void* const* d_in, const int* in_sizes, int n_in,
                              void* d_out, int out_size)
{
    const float* src = (const float*)d_in[0];
    const float* tgt = (const float*)d_in[1];
    const float* wts = (const float*)d_in[2];
    float* out = (float*)d_out;

    const int B = out_size / 12;            // 9 (R) + 3 (t) per batch
    const int N = in_sizes[2] / B;          // weights are (B,1,N)

    kabsch_kernel<<<B, RED_THREADS>>>(src, tgt, wts, out, N, B);
}

// round 9
// speedup vs baseline: 1.2209x; 1.1349x over previous
#include <cuda_runtime.h>
#include <math.h>
#include <stdint.h>

// ---------------------------------------------------------------------------
// Weighted Kabsch, fused, TMA-bulk staged.
// Per CTA (one batch): double-buffered cp.async.bulk tiles (3 instructions per
// tile from one elected thread, mbarrier completion), consumers read float4
// (LDS.128, conflict-free at 48B stride), accumulate 16 sufficient statistics,
// block-reduce; thread 0 runs the fp32 3x3 SVD + rigid-transform epilogue.
// ---------------------------------------------------------------------------

#define THREADS 128
#define TILE 512                 // points per tile (4 per thread)

struct __align__(16) Smem {
    float src[2][TILE * 3];      // 12 KB
    float tgt[2][TILE * 3];      // 12 KB
    float wgt[2][TILE];          //  4 KB
    float red[THREADS / 32][16];
    unsigned long long mbar[2];
};

__device__ __forceinline__ void mbar_init(uint32_t a, uint32_t cnt) {
    asm volatile("mbarrier.init.shared.b64 [%0], %1;" :: "r"(a), "r"(cnt) : "memory");
}
__device__ __forceinline__ void mbar_expect_tx(uint32_t a, uint32_t bytes) {
    asm volatile("mbarrier.arrive.expect_tx.shared.b64 _, [%0], %1;"
                 :: "r"(a), "r"(bytes) : "memory");
}
__device__ __forceinline__ void bulk_g2s(uint32_t sdst, const void* gsrc,
                                         uint32_t bytes, uint32_t mbar) {
    asm volatile(
        "cp.async.bulk.shared::cta.global.mbarrier::complete_tx::bytes [%0], [%1], %2, [%3];"
        :: "r"(sdst), "l"(gsrc), "r"(bytes), "r"(mbar) : "memory");
}
__device__ __forceinline__ void mbar_wait(uint32_t a, uint32_t parity) {
    uint32_t done;
    asm volatile(
        "{\n\t.reg .pred p;\n\t"
        "mbarrier.try_wait.parity.acquire.cta.shared::cta.b64 p, [%1], %2;\n\t"
        "selp.b32 %0, 1, 0, p;\n\t}"
        : "=r"(done) : "r"(a), "r"(parity) : "memory");
    if (!done) {
        asm volatile(
            "{\n\t.reg .pred P1;\n\t"
            "WL_%=:\n\t"
            "mbarrier.try_wait.parity.acquire.cta.shared::cta.b64 P1, [%0], %1, 0x989680;\n\t"
            "@P1 bra.uni WD_%=;\n\t"
            "bra.uni WL_%=;\n\t"
            "WD_%=:\n\t}"
            :: "r"(a), "r"(parity) : "memory");
    }
}

__device__ __forceinline__ float det3f(const float m[3][3]) {
    return m[0][0] * (m[1][1] * m[2][2] - m[1][2] * m[2][1])
         - m[0][1] * (m[1][0] * m[2][2] - m[1][2] * m[2][0])
         + m[0][2] * (m[1][0] * m[2][1] - m[1][1] * m[2][0]);
}

__global__ void __launch_bounds__(THREADS)
kabsch_kernel(const float* __restrict__ src,
              const float* __restrict__ tgt,
              const float* __restrict__ wts,
              float* __restrict__ out,
              int N, int B)
{
    __shared__ Smem sm;

    const int b = blockIdx.x;
    const int tid = threadIdx.x;
    const char* gS = (const char*)(src + (size_t)b * N * 3);
    const char* gT = (const char*)(tgt + (size_t)b * N * 3);
    const char* gW = (const char*)(wts + (size_t)b * N);

    const int ntiles = (N + TILE - 1) / TILE;

    const uint32_t smem_base = (uint32_t)__cvta_generic_to_shared(&sm);
    const uint32_t mb[2] = {
        (uint32_t)__cvta_generic_to_shared(&sm.mbar[0]),
        (uint32_t)__cvta_generic_to_shared(&sm.mbar[1])
    };
    const uint32_t sS[2] = { (uint32_t)__cvta_generic_to_shared(&sm.src[0][0]),
                             (uint32_t)__cvta_generic_to_shared(&sm.src[1][0]) };
    const uint32_t sT[2] = { (uint32_t)__cvta_generic_to_shared(&sm.tgt[0][0]),
                             (uint32_t)__cvta_generic_to_shared(&sm.tgt[1][0]) };
    const uint32_t sW[2] = { (uint32_t)__cvta_generic_to_shared(&sm.wgt[0][0]),
                             (uint32_t)__cvta_generic_to_shared(&sm.wgt[1][0]) };
    (void)smem_base;

    if (tid == 0) {
        mbar_init(mb[0], 1);
        mbar_init(mb[1], 1);
    }
    __syncthreads();

    // stage tile t into buffer bf (tid 0 only)
    auto stage = [&](int t, int bf) {
        const int npts = min(TILE, N - t * TILE);
        const uint32_t cbytes = (uint32_t)npts * 12u;
        const uint32_t wbytes = (uint32_t)npts * 4u;
        mbar_expect_tx(mb[bf], 2u * cbytes + wbytes);
        bulk_g2s(sS[bf], gS + (size_t)t * TILE * 12, cbytes, mb[bf]);
        bulk_g2s(sT[bf], gT + (size_t)t * TILE * 12, cbytes, mb[bf]);
        bulk_g2s(sW[bf], gW + (size_t)t * TILE * 4,  wbytes, mb[bf]);
    };

    float acc[16];
#pragma unroll
    for (int i = 0; i < 16; i++) acc[i] = 0.f;

    if (tid == 0) stage(0, 0);

    for (int t = 0; t < ntiles; t++) {
        const int bf = t & 1;
        if (tid == 0 && t + 1 < ntiles) stage(t + 1, bf ^ 1);

        mbar_wait(mb[bf], (uint32_t)(t >> 1) & 1u);

        const int npts = min(TILE, N - t * TILE);
        const float4* Sf4 = (const float4*)sm.src[bf];
        const float4* Tf4 = (const float4*)sm.tgt[bf];
        const float4* Wf4 = (const float4*)sm.wgt[bf];

        // thread handles points 4*tid .. 4*tid+3
        if (tid * 4 < npts) {
            float4 wv = Wf4[tid];
            float4 a0 = Sf4[tid * 3 + 0];
            float4 a1 = Sf4[tid * 3 + 1];
            float4 a2 = Sf4[tid * 3 + 2];
            float4 b0 = Tf4[tid * 3 + 0];
            float4 b1 = Tf4[tid * 3 + 1];
            float4 b2 = Tf4[tid * 3 + 2];

            const float sx[4][3] = {{a0.x, a0.y, a0.z},
                                    {a0.w, a1.x, a1.y},
                                    {a1.z, a1.w, a2.x},
                                    {a2.y, a2.z, a2.w}};
            const float tx[4][3] = {{b0.x, b0.y, b0.z},
                                    {b0.w, b1.x, b1.y},
                                    {b1.z, b1.w, b2.x},
                                    {b2.y, b2.z, b2.w}};
            const float wa[4] = {wv.x, wv.y, wv.z, wv.w};

#pragma unroll
            for (int p = 0; p < 4; p++) {
                const float w = wa[p];
                const float s0 = sx[p][0], s1 = sx[p][1], s2 = sx[p][2];
                const float wt0 = w * tx[p][0];
                const float wt1 = w * tx[p][1];
                const float wt2 = w * tx[p][2];
                acc[0] += w;
                acc[1] += w * s0;  acc[2] += w * s1;  acc[3] += w * s2;
                acc[4] += wt0;     acc[5] += wt1;     acc[6] += wt2;
                acc[7]  += wt0 * s0;  acc[8]  += wt0 * s1;  acc[9]  += wt0 * s2;
                acc[10] += wt1 * s0;  acc[11] += wt1 * s1;  acc[12] += wt1 * s2;
                acc[13] += wt2 * s0;  acc[14] += wt2 * s1;  acc[15] += wt2 * s2;
            }
        }
        __syncthreads();
    }

    // warp reduce
#pragma unroll
    for (int i = 0; i < 16; i++) {
#pragma unroll
        for (int o = 16; o > 0; o >>= 1)
            acc[i] += __shfl_down_sync(0xffffffffu, acc[i], o);
    }

    const int warp = tid >> 5;
    const int lane = tid & 31;
    if (lane == 0) {
#pragma unroll
        for (int i = 0; i < 16; i++) sm.red[warp][i] = acc[i];
    }
    __syncthreads();

    if (tid != 0) return;

    // ---- thread 0: finalize stats, fast fp32 3x3 SVD + epilogue ----
    float s[16];
#pragma unroll
    for (int i = 0; i < 16; i++) {
        float v = sm.red[0][i];
#pragma unroll
        for (int w = 1; w < THREADS / 32; w++) v += sm.red[w][i];
        s[i] = v;
    }

    const float Sw = s[0];
    const float Sx[3] = {s[1], s[2], s[3]};
    const float Tx[3] = {s[4], s[5], s[6]};
    const float M[3][3] = {{s[7], s[8], s[9]},
                           {s[10], s[11], s[12]},
                           {s[13], s[14], s[15]}};

    const float w = Sw + 1e-4f;
    const float winv = __fdividef(1.0f, w);
    float sc[3], tc[3];
#pragma unroll
    for (int i = 0; i < 3; i++) { sc[i] = Sx[i] * winv; tc[i] = Tx[i] * winv; }

    float A[3][3];
#pragma unroll
    for (int i = 0; i < 3; i++)
#pragma unroll
        for (int j = 0; j < 3; j++)
            A[i][j] = (M[i][j] - tc[i] * Sx[j] - Tx[i] * sc[j] + Sw * tc[i] * sc[j]) * winv;

    float Bm[3][3];
#pragma unroll
    for (int i = 0; i < 3; i++)
#pragma unroll
        for (int j = 0; j < 3; j++)
            Bm[i][j] = A[0][i] * A[0][j] + A[1][i] * A[1][j] + A[2][i] * A[2][j];

    float V[3][3] = {{1, 0, 0}, {0, 1, 0}, {0, 0, 1}};

    // cyclic Jacobi, 5 sweeps, fast divides, convergence skip
#pragma unroll 1
    for (int sweep = 0; sweep < 5; sweep++) {
#pragma unroll
        for (int pair = 0; pair < 3; pair++) {
            const int p = (pair == 2) ? 1 : 0;
            const int q = (pair == 0) ? 1 : 2;
            const float apq = Bm[p][q];
            const float app = Bm[p][p], aqq = Bm[q][q];
            if (apq * apq <= 1e-22f * app * aqq + 1e-38f) continue;
            const float tau = __fdividef(aqq - app, 2.0f * apq);
            const float t = __fdividef((tau >= 0.0f) ? 1.0f : -1.0f,
                                       fabsf(tau) + sqrtf(1.0f + tau * tau));
            const float c = rsqrtf(1.0f + t * t);
            const float sn = t * c;
#pragma unroll
            for (int k = 0; k < 3; k++) {
                const float bkp = Bm[k][p], bkq = Bm[k][q];
                Bm[k][p] = c * bkp - sn * bkq;
                Bm[k][q] = sn * bkp + c * bkq;
            }
#pragma unroll
            for (int k = 0; k < 3; k++) {
                const float bpk = Bm[p][k], bqk = Bm[q][k];
                Bm[p][k] = c * bpk - sn * bqk;
                Bm[q][k] = sn * bpk + c * bqk;
            }
#pragma unroll
            for (int k = 0; k < 3; k++) {
                const float vkp = V[k][p], vkq = V[k][q];
                V[k][p] = c * vkp - sn * vkq;
                V[k][q] = sn * vkp + c * vkq;
            }
        }
    }

    float lam[3] = {Bm[0][0], Bm[1][1], Bm[2][2]};
#pragma unroll
    for (int i = 0; i < 2; i++)
#pragma unroll
        for (int j = 0; j < 2 - i; j++)
            if (lam[j] < lam[j + 1]) {
                float tl = lam[j]; lam[j] = lam[j + 1]; lam[j + 1] = tl;
#pragma unroll
                for (int k = 0; k < 3; k++) {
                    float tv = V[k][j]; V[k][j] = V[k][j + 1]; V[k][j + 1] = tv;
                }
            }

    float U[3][3];
    float norms[3];
#pragma unroll
    for (int k = 0; k < 3; k++) {
        float uv[3];
#pragma unroll
        for (int i = 0; i < 3; i++)
            uv[i] = A[i][0] * V[0][k] + A[i][1] * V[1][k] + A[i][2] * V[2][k];
        const float nsq = uv[0] * uv[0] + uv[1] * uv[1] + uv[2] * uv[2];
        norms[k] = sqrtf(nsq);
        const float inv = (nsq > 1e-36f) ? rsqrtf(nsq) : 0.0f;
#pragma unroll
        for (int i = 0; i < 3; i++) U[i][k] = uv[i] * inv;
    }
    if (norms[2] < 1e-7f * (norms[0] + 1e-30f)) {
        U[0][2] = U[1][0] * U[2][1] - U[2][0] * U[1][1];
        U[1][2] = U[2][0] * U[0][1] - U[0][0] * U[2][1];
        U[2][2] = U[0][0] * U[1][1] - U[1][0] * U[0][1];
    }

    const float d = det3f(U) * det3f(V);

    float R[3][3];
#pragma unroll
    for (int i = 0; i < 3; i++)
#pragma unroll
        for (int j = 0; j < 3; j++)
            R[i][j] = U[i][0] * V[j][0] + U[i][1] * V[j][1] + d * U[i][2] * V[j][2];

    float t1[3], t[3];
#pragma unroll
    for (int i = 0; i < 3; i++)
        t1[i] = sc[i] - (R[0][i] * tc[0] + R[1][i] * tc[1] + R[2][i] * tc[2]);
#pragma unroll
    for (int i = 0; i < 3; i++)
        t[i] = -(R[i][0] * t1[0] + R[i][1] * t1[1] + R[i][2] * t1[2]);

    float* Rout = out + (size_t)b * 9;
    float* Tout = out + (size_t)B * 9 + (size_t)b * 3;
#pragma unroll
    for (int i = 0; i < 3; i++)
#pragma unroll
        for (int j = 0; j < 3; j++)
            Rout[i * 3 + j] = R[i][j];
#pragma unroll
    for (int i = 0; i < 3; i++) Tout[i] = t[i];
}

// ---------------------------------------------------------------------------

extern "C" void kernel_launch(void* const* d_in, const int* in_sizes, int n_in,
                              void* d_out, int out_size)
{
    const float* src = (const float*)d_in[0];
    const float* tgt = (const float*)d_in[1];
    const float* wts = (const float*)d_in[2];
    float* out = (float*)d_out;

    const int B = out_size / 12;            // 9 (R) + 3 (t) per batch
    const int N = in_sizes[2] / B;          // weights are (B,1,N)

    kabsch_kernel<<<B, THREADS>>>(src, tgt, wts, out, N, B);
}